// round 15
// baseline (speedup 1.0000x reference)
#include <cuda_runtime.h>
#include <stdint.h>

#define F_IN 128
#define HID  16
#define NCLS 8
#define MAX_N 100000

__device__ float g_deg [MAX_N];
__device__ float g_dinv[MAX_N];
__device__ float g_h1s [MAX_N * HID];   // dinv * (x@W1) — gathered by edge1
__device__ float g_agg1[MAX_N * HID];   // fp32 accumulator (self-loop init)
__device__ float g_h2s [MAX_N * NCLS];  // dinv * h2 — gathered by edge2
__device__ float g_agg2[MAX_N * NCLS];

__device__ __forceinline__ void red_add_v4(float* p, float4 v) {
    asm volatile("red.global.add.v4.f32 [%0], {%1, %2, %3, %4};"
                 :: "l"(p), "f"(v.x), "f"(v.y), "f"(v.z), "f"(v.w) : "memory");
}

// 0) deg init: self-loop contributes 1
__global__ void k_init_deg(int n) {
    int i = blockIdx.x * blockDim.x + threadIdx.x;
    if (i < n) g_deg[i] = 1.0f;
}

// 1) degree scatter, int4-vectorized (4 edges per thread)
__global__ void k_deg_scatter(const int* __restrict__ dst, int e) {
    int i = blockIdx.x * blockDim.x + threadIdx.x;
    int e4 = e >> 2;
    if (i < e4) {
        int4 d = ((const int4*)dst)[i];
        atomicAdd(&g_deg[d.x], 1.0f);
        atomicAdd(&g_deg[d.y], 1.0f);
        atomicAdd(&g_deg[d.z], 1.0f);
        atomicAdd(&g_deg[d.w], 1.0f);
    } else {
        int base = e4 * 4 + (i - e4);
        if (base < e) atomicAdd(&g_deg[dst[base]], 1.0f);
    }
}

// 2) xw1 fused (dinv inline): thread = (slot, jg), 4 nodes x 4 outputs.
#define XW_ND 4
__global__ void __launch_bounds__(256, 4) k_xw1(const float* __restrict__ x,
                                                const float* __restrict__ W1, int n) {
    __shared__ float4 sW1[F_IN * 4];  // sW1[k*4+jg] = W1[k][4jg..4jg+3]
    int t = threadIdx.x;
    for (int i = t; i < F_IN * 4; i += blockDim.x)
        sW1[i] = ((const float4*)W1)[i];
    __syncthreads();

    int slot = t >> 2;            // 0..63
    int jg   = t & 3;             // 0..3
    int base = blockIdx.x * (64 * XW_ND);

    int  node[XW_ND];
    bool ok  [XW_ND];
    #pragma unroll
    for (int i = 0; i < XW_ND; i++) {
        node[i] = base + i * 64 + slot;
        ok[i]   = node[i] < n;
    }

    float4 acc[XW_ND];
    #pragma unroll
    for (int i = 0; i < XW_ND; i++) acc[i] = make_float4(0.f, 0.f, 0.f, 0.f);

    #pragma unroll 4
    for (int k4 = 0; k4 < F_IN / 4; k4++) {
        float4 w0 = sW1[(k4 * 4 + 0) * 4 + jg];
        float4 w1 = sW1[(k4 * 4 + 1) * 4 + jg];
        float4 w2 = sW1[(k4 * 4 + 2) * 4 + jg];
        float4 w3 = sW1[(k4 * 4 + 3) * 4 + jg];
        float4 xv[XW_ND];
        #pragma unroll
        for (int i = 0; i < XW_ND; i++)
            xv[i] = ok[i] ? __ldg((const float4*)(x + (size_t)node[i] * F_IN) + k4)
                          : make_float4(0.f, 0.f, 0.f, 0.f);
        #pragma unroll
        for (int i = 0; i < XW_ND; i++) {
            acc[i].x = fmaf(xv[i].x, w0.x, acc[i].x);
            acc[i].y = fmaf(xv[i].x, w0.y, acc[i].y);
            acc[i].z = fmaf(xv[i].x, w0.z, acc[i].z);
            acc[i].w = fmaf(xv[i].x, w0.w, acc[i].w);
            acc[i].x = fmaf(xv[i].y, w1.x, acc[i].x);
            acc[i].y = fmaf(xv[i].y, w1.y, acc[i].y);
            acc[i].z = fmaf(xv[i].y, w1.z, acc[i].z);
            acc[i].w = fmaf(xv[i].y, w1.w, acc[i].w);
            acc[i].x = fmaf(xv[i].z, w2.x, acc[i].x);
            acc[i].y = fmaf(xv[i].z, w2.y, acc[i].y);
            acc[i].z = fmaf(xv[i].z, w2.z, acc[i].z);
            acc[i].w = fmaf(xv[i].z, w2.w, acc[i].w);
            acc[i].x = fmaf(xv[i].w, w3.x, acc[i].x);
            acc[i].y = fmaf(xv[i].w, w3.y, acc[i].y);
            acc[i].z = fmaf(xv[i].w, w3.z, acc[i].z);
            acc[i].w = fmaf(xv[i].w, w3.w, acc[i].w);
        }
    }

    #pragma unroll
    for (int i = 0; i < XW_ND; i++) {
        if (!ok[i]) continue;
        float di = rsqrtf(g_deg[node[i]]);
        if (jg == 0) g_dinv[node[i]] = di;
        float4 hs = make_float4(di * acc[i].x, di * acc[i].y,
                                di * acc[i].z, di * acc[i].w);
        *(float4*)(g_h1s  + node[i] * HID + jg * 4) = hs;
        *(float4*)(g_agg1 + node[i] * HID + jg * 4) = hs;
    }
}

// 3) layer-1 edge scatter: 4 threads/edge, 4 independent edges/thread. [idx 3]
__global__ void k_edge1(const int* __restrict__ src,
                        const int* __restrict__ dst, int e) {
    int h4 = (e + 3) >> 2;
    long long gid = (long long)blockIdx.x * blockDim.x + threadIdx.x;
    int q = (int)(gid >> 2);
    int j = (int)(gid & 3);
    if (q >= h4) return;

    int ed[4];
    bool ok[4];
    #pragma unroll
    for (int i = 0; i < 4; i++) {
        ed[i] = q + i * h4;
        ok[i] = ed[i] < e;
    }
    int s[4], d[4];
    #pragma unroll
    for (int i = 0; i < 4; i++) {
        s[i] = ok[i] ? src[ed[i]] : 0;
        d[i] = ok[i] ? dst[ed[i]] : 0;
    }
    float4 hv[4];
    #pragma unroll
    for (int i = 0; i < 4; i++)
        hv[i] = ok[i] ? *(const float4*)(g_h1s + s[i] * HID + j * 4)
                      : make_float4(0.f, 0.f, 0.f, 0.f);
    #pragma unroll
    for (int i = 0; i < 4; i++)
        if (ok[i])
            red_add_v4(g_agg1 + d[i] * HID + j * 4, hv[i]);
}

// 4) h2 = relu(dinv*agg1 + b1) @ W2; h2s = dinv*h2; agg2 = h2s (self loop)
__global__ void k_layer2(const float* __restrict__ b1,
                         const float* __restrict__ W2, int n) {
    __shared__ float sW2[HID * NCLS];
    __shared__ float sb1[HID];
    if (threadIdx.x < HID * NCLS) sW2[threadIdx.x] = W2[threadIdx.x];
    if (threadIdx.x < HID) sb1[threadIdx.x] = b1[threadIdx.x];
    __syncthreads();

    int gid = blockIdx.x * blockDim.x + threadIdx.x;
    int node = gid / NCLS;
    int c    = gid % NCLS;
    if (node >= n) return;

    float di = g_dinv[node];
    float acc = 0.0f;
    #pragma unroll
    for (int j = 0; j < HID; j++) {
        float v = fmaf(di, g_agg1[node * HID + j], sb1[j]);
        v = fmaxf(v, 0.0f);
        acc = fmaf(v, sW2[j * NCLS + c], acc);
    }
    float hs = di * acc;
    g_h2s [node * NCLS + c] = hs;
    g_agg2[node * NCLS + c] = hs;
}

// 5) layer-2 edge scatter: 2 threads/edge, 4 independent edges/thread
__global__ void k_edge2(const int* __restrict__ src,
                        const int* __restrict__ dst, int e) {
    int h4 = (e + 3) >> 2;
    long long gid = (long long)blockIdx.x * blockDim.x + threadIdx.x;
    int q = (int)(gid >> 1);
    int j = (int)(gid & 1);
    if (q >= h4) return;

    int ed[4];
    bool ok[4];
    #pragma unroll
    for (int i = 0; i < 4; i++) {
        ed[i] = q + i * h4;
        ok[i] = ed[i] < e;
    }
    int s[4], d[4];
    #pragma unroll
    for (int i = 0; i < 4; i++) {
        s[i] = ok[i] ? src[ed[i]] : 0;
        d[i] = ok[i] ? dst[ed[i]] : 0;
    }
    float4 hv[4];
    #pragma unroll
    for (int i = 0; i < 4; i++)
        hv[i] = ok[i] ? *(const float4*)(g_h2s + s[i] * NCLS + j * 4)
                      : make_float4(0.f, 0.f, 0.f, 0.f);
    #pragma unroll
    for (int i = 0; i < 4; i++)
        if (ok[i])
            red_add_v4(g_agg2 + d[i] * NCLS + j * 4, hv[i]);
}

// 6) logits = dinv*agg2 + b2 -> log_softmax
__global__ void k_logsoftmax(const float* __restrict__ b2,
                             float* __restrict__ out, int n) {
    __shared__ float sb2[NCLS];
    if (threadIdx.x < NCLS) sb2[threadIdx.x] = b2[threadIdx.x];
    __syncthreads();

    int i = blockIdx.x * blockDim.x + threadIdx.x;
    if (i >= n) return;

    float di = g_dinv[i];
    float4 a = *(const float4*)(g_agg2 + i * NCLS);
    float4 b = *(const float4*)(g_agg2 + i * NCLS + 4);
    float z[NCLS] = {fmaf(di, a.x, sb2[0]), fmaf(di, a.y, sb2[1]),
                     fmaf(di, a.z, sb2[2]), fmaf(di, a.w, sb2[3]),
                     fmaf(di, b.x, sb2[4]), fmaf(di, b.y, sb2[5]),
                     fmaf(di, b.z, sb2[6]), fmaf(di, b.w, sb2[7])};
    float m = z[0];
    #pragma unroll
    for (int c = 1; c < NCLS; c++) m = fmaxf(m, z[c]);
    float sum = 0.0f;
    #pragma unroll
    for (int c = 0; c < NCLS; c++) sum += expf(z[c] - m);
    float lse = m + logf(sum);
    *(float4*)(out + i * NCLS)     = make_float4(z[0]-lse, z[1]-lse, z[2]-lse, z[3]-lse);
    *(float4*)(out + i * NCLS + 4) = make_float4(z[4]-lse, z[5]-lse, z[6]-lse, z[7]-lse);
}

// ---------------------------------------------------------------------------
extern "C" void kernel_launch(void* const* d_in, const int* in_sizes, int n_in,
                              void* d_out, int out_size) {
    const float* x  = (const float*)d_in[0];
    const int*   ei = (const int*)d_in[1];    // [2, E] int32
    const float* W1 = (const float*)d_in[2];
    const float* b1 = (const float*)d_in[3];
    const float* W2 = (const float*)d_in[4];
    const float* b2 = (const float*)d_in[5];
    float*       out = (float*)d_out;

    const int n = in_sizes[0] / F_IN;      // 100000
    const int e = in_sizes[1] / 2;         // 3200000
    const int* src = ei;
    const int* dst = ei + e;

    const int T = 256;
    int e4t = (e >> 2) + (e & 3);
    int h4  = (e + 3) >> 2;

    k_init_deg<<<(n + T - 1) / T, T>>>(n);                              // 0
    k_deg_scatter<<<(e4t + T - 1) / T, T>>>(dst, e);                    // 1
    k_xw1<<<(n + 64 * XW_ND - 1) / (64 * XW_ND), T>>>(x, W1, n);        // 2
    {
        long long total = (long long)h4 * 4;
        k_edge1<<<(unsigned)((total + T - 1) / T), T>>>(src, dst, e);   // 3 (profiled)
    }
    k_layer2<<<((long long)n * NCLS + T - 1) / T, T>>>(b1, W2, n);      // 4
    {
        long long total = (long long)h4 * 2;
        k_edge2<<<(unsigned)((total + T - 1) / T), T>>>(src, dst, e);   // 5
    }
    k_logsoftmax<<<(n + T - 1) / T, T>>>(b2, out, n);                   // 6
}

// round 16
// speedup vs baseline: 1.0266x; 1.0266x over previous
#include <cuda_runtime.h>
#include <stdint.h>

#define F_IN 128
#define HID  16
#define NCLS 8
#define MAX_N 100000

// Zero-initialized at module load; k_logsoftmax re-zeros g_deg each call.
__device__ float g_deg [MAX_N];          // edge count per dst (NO self loop)
__device__ float g_dinv[MAX_N];
__device__ float g_h1s [MAX_N * HID];    // dinv * (x@W1) — gathered by edge1
__device__ float g_agg1[MAX_N * HID];    // fp32 accumulator (self-loop init)
__device__ float g_h2s [MAX_N * NCLS];   // dinv * h2 — gathered by edge2
__device__ float g_agg2[MAX_N * NCLS];

__device__ __forceinline__ void red_add_v4(float* p, float4 v) {
    asm volatile("red.global.add.v4.f32 [%0], {%1, %2, %3, %4};"
                 :: "l"(p), "f"(v.x), "f"(v.y), "f"(v.z), "f"(v.w) : "memory");
}

// 0) degree scatter, int4-vectorized (4 edges per thread); g_deg starts zeroed
__global__ void k_deg_scatter(const int* __restrict__ dst, int e) {
    int i = blockIdx.x * blockDim.x + threadIdx.x;
    int e4 = e >> 2;
    if (i < e4) {
        int4 d = ((const int4*)dst)[i];
        atomicAdd(&g_deg[d.x], 1.0f);
        atomicAdd(&g_deg[d.y], 1.0f);
        atomicAdd(&g_deg[d.z], 1.0f);
        atomicAdd(&g_deg[d.w], 1.0f);
    } else {
        int base = e4 * 4 + (i - e4);
        if (base < e) atomicAdd(&g_deg[dst[base]], 1.0f);
    }
}

// 1) xw1 fused (dinv inline, +1 for self loop): thread = (slot, jg), 4 nodes x 4 out.
#define XW_ND 4
__global__ void __launch_bounds__(256, 4) k_xw1(const float* __restrict__ x,
                                                const float* __restrict__ W1, int n) {
    __shared__ float4 sW1[F_IN * 4];  // sW1[k*4+jg] = W1[k][4jg..4jg+3]
    int t = threadIdx.x;
    for (int i = t; i < F_IN * 4; i += blockDim.x)
        sW1[i] = ((const float4*)W1)[i];
    __syncthreads();

    int slot = t >> 2;            // 0..63
    int jg   = t & 3;             // 0..3
    int base = blockIdx.x * (64 * XW_ND);

    int  node[XW_ND];
    bool ok  [XW_ND];
    #pragma unroll
    for (int i = 0; i < XW_ND; i++) {
        node[i] = base + i * 64 + slot;
        ok[i]   = node[i] < n;
    }

    float4 acc[XW_ND];
    #pragma unroll
    for (int i = 0; i < XW_ND; i++) acc[i] = make_float4(0.f, 0.f, 0.f, 0.f);

    #pragma unroll 4
    for (int k4 = 0; k4 < F_IN / 4; k4++) {
        float4 w0 = sW1[(k4 * 4 + 0) * 4 + jg];
        float4 w1 = sW1[(k4 * 4 + 1) * 4 + jg];
        float4 w2 = sW1[(k4 * 4 + 2) * 4 + jg];
        float4 w3 = sW1[(k4 * 4 + 3) * 4 + jg];
        float4 xv[XW_ND];
        #pragma unroll
        for (int i = 0; i < XW_ND; i++)
            xv[i] = ok[i] ? __ldg((const float4*)(x + (size_t)node[i] * F_IN) + k4)
                          : make_float4(0.f, 0.f, 0.f, 0.f);
        #pragma unroll
        for (int i = 0; i < XW_ND; i++) {
            acc[i].x = fmaf(xv[i].x, w0.x, acc[i].x);
            acc[i].y = fmaf(xv[i].x, w0.y, acc[i].y);
            acc[i].z = fmaf(xv[i].x, w0.z, acc[i].z);
            acc[i].w = fmaf(xv[i].x, w0.w, acc[i].w);
            acc[i].x = fmaf(xv[i].y, w1.x, acc[i].x);
            acc[i].y = fmaf(xv[i].y, w1.y, acc[i].y);
            acc[i].z = fmaf(xv[i].y, w1.z, acc[i].z);
            acc[i].w = fmaf(xv[i].y, w1.w, acc[i].w);
            acc[i].x = fmaf(xv[i].z, w2.x, acc[i].x);
            acc[i].y = fmaf(xv[i].z, w2.y, acc[i].y);
            acc[i].z = fmaf(xv[i].z, w2.z, acc[i].z);
            acc[i].w = fmaf(xv[i].z, w2.w, acc[i].w);
            acc[i].x = fmaf(xv[i].w, w3.x, acc[i].x);
            acc[i].y = fmaf(xv[i].w, w3.y, acc[i].y);
            acc[i].z = fmaf(xv[i].w, w3.z, acc[i].z);
            acc[i].w = fmaf(xv[i].w, w3.w, acc[i].w);
        }
    }

    #pragma unroll
    for (int i = 0; i < XW_ND; i++) {
        if (!ok[i]) continue;
        float di = rsqrtf(g_deg[node[i]] + 1.0f);   // +1 = self loop
        if (jg == 0) g_dinv[node[i]] = di;
        float4 hs = make_float4(di * acc[i].x, di * acc[i].y,
                                di * acc[i].z, di * acc[i].w);
        *(float4*)(g_h1s  + node[i] * HID + jg * 4) = hs;
        *(float4*)(g_agg1 + node[i] * HID + jg * 4) = hs;
    }
}

// 2) layer-1 edge scatter: 4 threads/edge, 2 edges/thread, v4 RED (best shape)
__global__ void k_edge1(const int* __restrict__ src,
                        const int* __restrict__ dst, int e) {
    int h = (e + 1) >> 1;
    long long gid = (long long)blockIdx.x * blockDim.x + threadIdx.x;
    int q = (int)(gid >> 2);
    int j = (int)(gid & 3);
    if (q >= h) return;
    int eA = q, eB = q + h;
    bool hasB = eB < e;

    int sA = src[eA], dA = dst[eA];
    int sB = 0, dB = 0;
    if (hasB) { sB = src[eB]; dB = dst[eB]; }

    float4 hA = *(const float4*)(g_h1s + sA * HID + j * 4);
    red_add_v4(g_agg1 + dA * HID + j * 4, hA);
    if (hasB) {
        float4 hB = *(const float4*)(g_h1s + sB * HID + j * 4);
        red_add_v4(g_agg1 + dB * HID + j * 4, hB);
    }
}

// 3) h2 = relu(dinv*agg1 + b1) @ W2; h2s = dinv*h2; agg2 = h2s  [profiled idx 3]
__global__ void k_layer2(const float* __restrict__ b1,
                         const float* __restrict__ W2, int n) {
    __shared__ float sW2[HID * NCLS];
    __shared__ float sb1[HID];
    if (threadIdx.x < HID * NCLS) sW2[threadIdx.x] = W2[threadIdx.x];
    if (threadIdx.x < HID) sb1[threadIdx.x] = b1[threadIdx.x];
    __syncthreads();

    int gid = blockIdx.x * blockDim.x + threadIdx.x;
    int node = gid / NCLS;
    int c    = gid % NCLS;
    if (node >= n) return;

    float di = g_dinv[node];
    float acc = 0.0f;
    #pragma unroll
    for (int j = 0; j < HID; j++) {
        float v = fmaf(di, g_agg1[node * HID + j], sb1[j]);
        v = fmaxf(v, 0.0f);
        acc = fmaf(v, sW2[j * NCLS + c], acc);
    }
    float hs = di * acc;
    g_h2s [node * NCLS + c] = hs;
    g_agg2[node * NCLS + c] = hs;
}

// 4) layer-2 edge scatter: 2 threads/edge, 2 edges/thread, v4 RED
__global__ void k_edge2(const int* __restrict__ src,
                        const int* __restrict__ dst, int e) {
    int h = (e + 1) >> 1;
    long long gid = (long long)blockIdx.x * blockDim.x + threadIdx.x;
    int q = (int)(gid >> 1);
    int j = (int)(gid & 1);
    if (q >= h) return;
    int eA = q, eB = q + h;
    bool hasB = eB < e;

    int sA = src[eA], dA = dst[eA];
    int sB = 0, dB = 0;
    if (hasB) { sB = src[eB]; dB = dst[eB]; }

    float4 hA = *(const float4*)(g_h2s + sA * NCLS + j * 4);
    red_add_v4(g_agg2 + dA * NCLS + j * 4, hA);
    if (hasB) {
        float4 hB = *(const float4*)(g_h2s + sB * NCLS + j * 4);
        red_add_v4(g_agg2 + dB * NCLS + j * 4, hB);
    }
}

// 5) logits = dinv*agg2 + b2 -> log_softmax; re-zero g_deg for next invocation
__global__ void k_logsoftmax(const float* __restrict__ b2,
                             float* __restrict__ out, int n) {
    __shared__ float sb2[NCLS];
    if (threadIdx.x < NCLS) sb2[threadIdx.x] = b2[threadIdx.x];
    __syncthreads();

    int i = blockIdx.x * blockDim.x + threadIdx.x;
    if (i >= n) return;

    g_deg[i] = 0.0f;   // reset for next kernel_launch call (deterministic)

    float di = g_dinv[i];
    float4 a = *(const float4*)(g_agg2 + i * NCLS);
    float4 b = *(const float4*)(g_agg2 + i * NCLS + 4);
    float z[NCLS] = {fmaf(di, a.x, sb2[0]), fmaf(di, a.y, sb2[1]),
                     fmaf(di, a.z, sb2[2]), fmaf(di, a.w, sb2[3]),
                     fmaf(di, b.x, sb2[4]), fmaf(di, b.y, sb2[5]),
                     fmaf(di, b.z, sb2[6]), fmaf(di, b.w, sb2[7])};
    float m = z[0];
    #pragma unroll
    for (int c = 1; c < NCLS; c++) m = fmaxf(m, z[c]);
    float sum = 0.0f;
    #pragma unroll
    for (int c = 0; c < NCLS; c++) sum += expf(z[c] - m);
    float lse = m + logf(sum);
    *(float4*)(out + i * NCLS)     = make_float4(z[0]-lse, z[1]-lse, z[2]-lse, z[3]-lse);
    *(float4*)(out + i * NCLS + 4) = make_float4(z[4]-lse, z[5]-lse, z[6]-lse, z[7]-lse);
}

// ---------------------------------------------------------------------------
extern "C" void kernel_launch(void* const* d_in, const int* in_sizes, int n_in,
                              void* d_out, int out_size) {
    const float* x  = (const float*)d_in[0];
    const int*   ei = (const int*)d_in[1];    // [2, E] int32
    const float* W1 = (const float*)d_in[2];
    const float* b1 = (const float*)d_in[3];
    const float* W2 = (const float*)d_in[4];
    const float* b2 = (const float*)d_in[5];
    float*       out = (float*)d_out;

    const int n = in_sizes[0] / F_IN;      // 100000
    const int e = in_sizes[1] / 2;         // 3200000
    const int* src = ei;
    const int* dst = ei + e;

    const int T = 256;
    int e4t = (e >> 2) + (e & 3);

    k_deg_scatter<<<(e4t + T - 1) / T, T>>>(dst, e);                    // 0
    k_xw1<<<(n + 64 * XW_ND - 1) / (64 * XW_ND), T>>>(x, W1, n);        // 1
    {
        long long total = (long long)((e + 1) >> 1) * 4;
        k_edge1<<<(unsigned)((total + T - 1) / T), T>>>(src, dst, e);   // 2
    }
    k_layer2<<<((long long)n * NCLS + T - 1) / T, T>>>(b1, W2, n);      // 3 (profiled)
    {
        long long total = (long long)((e + 1) >> 1) * 2;
        k_edge2<<<(unsigned)((total + T - 1) / T), T>>>(src, dst, e);   // 4
    }
    k_logsoftmax<<<(n + T - 1) / T, T>>>(b2, out, n);                   // 5
}

// round 17
// speedup vs baseline: 1.0426x; 1.0156x over previous
#include <cuda_runtime.h>
#include <stdint.h>

#define F_IN 128
#define HID  16
#define NCLS 8
#define MAX_N 100000

// Zero-initialized at module load; k_logsoftmax re-zeros g_deg each call.
__device__ float g_deg [MAX_N];          // edge count per dst (NO self loop)
__device__ float g_dinv[MAX_N];
__device__ float g_h1s [MAX_N * HID];    // dinv * (x@W1) — gathered by edge1
__device__ float g_agg1[MAX_N * HID];    // fp32 accumulator (self-loop init)
__device__ float g_h2s [MAX_N * NCLS];   // dinv * h2 — gathered by edge2
__device__ float g_agg2[MAX_N * NCLS];

__device__ __forceinline__ void red_add_v4(float* p, float4 v) {
    asm volatile("red.global.add.v4.f32 [%0], {%1, %2, %3, %4};"
                 :: "l"(p), "f"(v.x), "f"(v.y), "f"(v.z), "f"(v.w) : "memory");
}

// 0) degree scatter, int4-vectorized (4 edges per thread); g_deg starts zeroed
__global__ void k_deg_scatter(const int* __restrict__ dst, int e) {
    int i = blockIdx.x * blockDim.x + threadIdx.x;
    int e4 = e >> 2;
    if (i < e4) {
        int4 d = ((const int4*)dst)[i];
        atomicAdd(&g_deg[d.x], 1.0f);
        atomicAdd(&g_deg[d.y], 1.0f);
        atomicAdd(&g_deg[d.z], 1.0f);
        atomicAdd(&g_deg[d.w], 1.0f);
    } else {
        int base = e4 * 4 + (i - e4);
        if (base < e) atomicAdd(&g_deg[dst[base]], 1.0f);
    }
}

// 1) xw1 fused (dinv inline, +1 for self loop): thread = (slot, jg), 4 nodes x 4 out.
#define XW_ND 4
__global__ void __launch_bounds__(256, 4) k_xw1(const float* __restrict__ x,
                                                const float* __restrict__ W1, int n) {
    __shared__ float4 sW1[F_IN * 4];  // sW1[k*4+jg] = W1[k][4jg..4jg+3]
    int t = threadIdx.x;
    for (int i = t; i < F_IN * 4; i += blockDim.x)
        sW1[i] = ((const float4*)W1)[i];
    __syncthreads();

    int slot = t >> 2;            // 0..63
    int jg   = t & 3;             // 0..3
    int base = blockIdx.x * (64 * XW_ND);

    int  node[XW_ND];
    bool ok  [XW_ND];
    #pragma unroll
    for (int i = 0; i < XW_ND; i++) {
        node[i] = base + i * 64 + slot;
        ok[i]   = node[i] < n;
    }

    float4 acc[XW_ND];
    #pragma unroll
    for (int i = 0; i < XW_ND; i++) acc[i] = make_float4(0.f, 0.f, 0.f, 0.f);

    #pragma unroll 4
    for (int k4 = 0; k4 < F_IN / 4; k4++) {
        float4 w0 = sW1[(k4 * 4 + 0) * 4 + jg];
        float4 w1 = sW1[(k4 * 4 + 1) * 4 + jg];
        float4 w2 = sW1[(k4 * 4 + 2) * 4 + jg];
        float4 w3 = sW1[(k4 * 4 + 3) * 4 + jg];
        float4 xv[XW_ND];
        #pragma unroll
        for (int i = 0; i < XW_ND; i++)
            xv[i] = ok[i] ? __ldg((const float4*)(x + (size_t)node[i] * F_IN) + k4)
                          : make_float4(0.f, 0.f, 0.f, 0.f);
        #pragma unroll
        for (int i = 0; i < XW_ND; i++) {
            acc[i].x = fmaf(xv[i].x, w0.x, acc[i].x);
            acc[i].y = fmaf(xv[i].x, w0.y, acc[i].y);
            acc[i].z = fmaf(xv[i].x, w0.z, acc[i].z);
            acc[i].w = fmaf(xv[i].x, w0.w, acc[i].w);
            acc[i].x = fmaf(xv[i].y, w1.x, acc[i].x);
            acc[i].y = fmaf(xv[i].y, w1.y, acc[i].y);
            acc[i].z = fmaf(xv[i].y, w1.z, acc[i].z);
            acc[i].w = fmaf(xv[i].y, w1.w, acc[i].w);
            acc[i].x = fmaf(xv[i].z, w2.x, acc[i].x);
            acc[i].y = fmaf(xv[i].z, w2.y, acc[i].y);
            acc[i].z = fmaf(xv[i].z, w2.z, acc[i].z);
            acc[i].w = fmaf(xv[i].z, w2.w, acc[i].w);
            acc[i].x = fmaf(xv[i].w, w3.x, acc[i].x);
            acc[i].y = fmaf(xv[i].w, w3.y, acc[i].y);
            acc[i].z = fmaf(xv[i].w, w3.z, acc[i].z);
            acc[i].w = fmaf(xv[i].w, w3.w, acc[i].w);
        }
    }

    #pragma unroll
    for (int i = 0; i < XW_ND; i++) {
        if (!ok[i]) continue;
        float di = rsqrtf(g_deg[node[i]] + 1.0f);   // +1 = self loop
        if (jg == 0) g_dinv[node[i]] = di;
        float4 hs = make_float4(di * acc[i].x, di * acc[i].y,
                                di * acc[i].z, di * acc[i].w);
        *(float4*)(g_h1s  + node[i] * HID + jg * 4) = hs;
        *(float4*)(g_agg1 + node[i] * HID + jg * 4) = hs;
    }
}

// 2) layer-1 edge scatter: 4 threads/edge, 2 edges/thread, v4 RED (best shape)
__global__ void k_edge1(const int* __restrict__ src,
                        const int* __restrict__ dst, int e) {
    int h = (e + 1) >> 1;
    long long gid = (long long)blockIdx.x * blockDim.x + threadIdx.x;
    int q = (int)(gid >> 2);
    int j = (int)(gid & 3);
    if (q >= h) return;
    int eA = q, eB = q + h;
    bool hasB = eB < e;

    int sA = src[eA], dA = dst[eA];
    int sB = 0, dB = 0;
    if (hasB) { sB = src[eB]; dB = dst[eB]; }

    float4 hA = *(const float4*)(g_h1s + sA * HID + j * 4);
    red_add_v4(g_agg1 + dA * HID + j * 4, hA);
    if (hasB) {
        float4 hB = *(const float4*)(g_h1s + sB * HID + j * 4);
        red_add_v4(g_agg1 + dB * HID + j * 4, hB);
    }
}

// 3) layer2, 1 thread/node: 4x LDG.128 row read, 128 reg FMAs, wide stores.
//    h2 = relu(dinv*agg1 + b1) @ W2; h2s = dinv*h2; agg2 = h2s. [profiled idx 3]
__global__ void k_layer2(const float* __restrict__ b1,
                         const float* __restrict__ W2, int n) {
    __shared__ float sW2[HID * NCLS];
    __shared__ float sb1[HID];
    if (threadIdx.x < HID * NCLS) sW2[threadIdx.x] = W2[threadIdx.x];
    if (threadIdx.x < HID) sb1[threadIdx.x] = b1[threadIdx.x];
    __syncthreads();

    int node = blockIdx.x * blockDim.x + threadIdx.x;
    if (node >= n) return;

    float di = g_dinv[node];
    float v[HID];
    #pragma unroll
    for (int g = 0; g < 4; g++) {
        float4 a = *(const float4*)(g_agg1 + node * HID + g * 4);
        v[g*4+0] = fmaxf(fmaf(di, a.x, sb1[g*4+0]), 0.f);
        v[g*4+1] = fmaxf(fmaf(di, a.y, sb1[g*4+1]), 0.f);
        v[g*4+2] = fmaxf(fmaf(di, a.z, sb1[g*4+2]), 0.f);
        v[g*4+3] = fmaxf(fmaf(di, a.w, sb1[g*4+3]), 0.f);
    }

    float acc[NCLS];
    #pragma unroll
    for (int c = 0; c < NCLS; c++) acc[c] = 0.f;
    #pragma unroll
    for (int j = 0; j < HID; j++) {
        float vj = v[j];
        #pragma unroll
        for (int c = 0; c < NCLS; c++)
            acc[c] = fmaf(vj, sW2[j * NCLS + c], acc[c]);
    }

    float4 o0 = make_float4(di*acc[0], di*acc[1], di*acc[2], di*acc[3]);
    float4 o1 = make_float4(di*acc[4], di*acc[5], di*acc[6], di*acc[7]);
    *(float4*)(g_h2s  + node * NCLS)     = o0;
    *(float4*)(g_h2s  + node * NCLS + 4) = o1;
    *(float4*)(g_agg2 + node * NCLS)     = o0;
    *(float4*)(g_agg2 + node * NCLS + 4) = o1;
}

// 4) layer-2 edge scatter: 2 threads/edge, 2 edges/thread, v4 RED
__global__ void k_edge2(const int* __restrict__ src,
                        const int* __restrict__ dst, int e) {
    int h = (e + 1) >> 1;
    long long gid = (long long)blockIdx.x * blockDim.x + threadIdx.x;
    int q = (int)(gid >> 1);
    int j = (int)(gid & 1);
    if (q >= h) return;
    int eA = q, eB = q + h;
    bool hasB = eB < e;

    int sA = src[eA], dA = dst[eA];
    int sB = 0, dB = 0;
    if (hasB) { sB = src[eB]; dB = dst[eB]; }

    float4 hA = *(const float4*)(g_h2s + sA * NCLS + j * 4);
    red_add_v4(g_agg2 + dA * NCLS + j * 4, hA);
    if (hasB) {
        float4 hB = *(const float4*)(g_h2s + sB * NCLS + j * 4);
        red_add_v4(g_agg2 + dB * NCLS + j * 4, hB);
    }
}

// 5) logits = dinv*agg2 + b2 -> log_softmax; re-zero g_deg for next invocation
__global__ void k_logsoftmax(const float* __restrict__ b2,
                             float* __restrict__ out, int n) {
    __shared__ float sb2[NCLS];
    if (threadIdx.x < NCLS) sb2[threadIdx.x] = b2[threadIdx.x];
    __syncthreads();

    int i = blockIdx.x * blockDim.x + threadIdx.x;
    if (i >= n) return;

    g_deg[i] = 0.0f;   // reset for next kernel_launch call (deterministic)

    float di = g_dinv[i];
    float4 a = *(const float4*)(g_agg2 + i * NCLS);
    float4 b = *(const float4*)(g_agg2 + i * NCLS + 4);
    float z[NCLS] = {fmaf(di, a.x, sb2[0]), fmaf(di, a.y, sb2[1]),
                     fmaf(di, a.z, sb2[2]), fmaf(di, a.w, sb2[3]),
                     fmaf(di, b.x, sb2[4]), fmaf(di, b.y, sb2[5]),
                     fmaf(di, b.z, sb2[6]), fmaf(di, b.w, sb2[7])};
    float m = z[0];
    #pragma unroll
    for (int c = 1; c < NCLS; c++) m = fmaxf(m, z[c]);
    float sum = 0.0f;
    #pragma unroll
    for (int c = 0; c < NCLS; c++) sum += expf(z[c] - m);
    float lse = m + logf(sum);
    *(float4*)(out + i * NCLS)     = make_float4(z[0]-lse, z[1]-lse, z[2]-lse, z[3]-lse);
    *(float4*)(out + i * NCLS + 4) = make_float4(z[4]-lse, z[5]-lse, z[6]-lse, z[7]-lse);
}

// ---------------------------------------------------------------------------
extern "C" void kernel_launch(void* const* d_in, const int* in_sizes, int n_in,
                              void* d_out, int out_size) {
    const float* x  = (const float*)d_in[0];
    const int*   ei = (const int*)d_in[1];    // [2, E] int32
    const float* W1 = (const float*)d_in[2];
    const float* b1 = (const float*)d_in[3];
    const float* W2 = (const float*)d_in[4];
    const float* b2 = (const float*)d_in[5];
    float*       out = (float*)d_out;

    const int n = in_sizes[0] / F_IN;      // 100000
    const int e = in_sizes[1] / 2;         // 3200000
    const int* src = ei;
    const int* dst = ei + e;

    const int T = 256;
    int e4t = (e >> 2) + (e & 3);

    k_deg_scatter<<<(e4t + T - 1) / T, T>>>(dst, e);                    // 0
    k_xw1<<<(n + 64 * XW_ND - 1) / (64 * XW_ND), T>>>(x, W1, n);        // 1
    {
        long long total = (long long)((e + 1) >> 1) * 4;
        k_edge1<<<(unsigned)((total + T - 1) / T), T>>>(src, dst, e);   // 2
    }
    k_layer2<<<(n + T - 1) / T, T>>>(b1, W2, n);                        // 3 (profiled)
    {
        long long total = (long long)((e + 1) >> 1) * 2;
        k_edge2<<<(unsigned)((total + T - 1) / T), T>>>(src, dst, e);   // 4
    }
    k_logsoftmax<<<(n + T - 1) / T, T>>>(b2, out, n);                   // 5
}